// round 12
// baseline (speedup 1.0000x reference)
#include <cuda_runtime.h>
#include <cstdint>

// Problem sizes (fixed by reference)
#define S_DIM  1024
#define P_DIM  8
#define N_PTS  8192            // S*P flattened colors

// NOTE: the reference sorts palette rows per column before the softmin, but
// the final loss is a MEAN over all queries -> permutation-invariant. The
// sort is a no-op on the output scalar and is omitted entirely.

#define Q_PER_THREAD 2         // 1 packed pair per thread
#define BLK          256       // 8 warps/block
#define GX           16        // query columns: 16 * 512 = 8192 queries
#define NCH          37        // key chunks; grid 16 x 37 = 592 = 4 blocks/SM
#define MC           222       // ceil(8192/37); last chunk = 200
#define QCOL         (BLK * Q_PER_THREAD)   // 512 queries per column

// Coordinates pre-scaled by LG2E so u = sqrt(s') = log2(e)*dist and
// exp(-dist) = ex2(-u): zero extra FMA for the exponent argument.
#define LG2E  1.4426950408889634f
#define ILG2E 0.6931471805599453f

// Static device scratch (no allocations allowed)
__device__ float4 g_scratch[NCH * N_PTS];    // per-chunk partials {sum_w, accx, accy, accz}
__device__ unsigned int g_cnt[GX];           // per-column completion counters (reset by reducer)

// ---- packed f32x2 helpers -------------------------------------------------
union f2u { float2 f; unsigned long long u; };
__device__ __forceinline__ float2 ffma2(float2 a, float2 b, float2 c) {
    f2u A, B, C, D; A.f = a; B.f = b; C.f = c;
    asm("fma.rn.f32x2 %0, %1, %2, %3;" : "=l"(D.u) : "l"(A.u), "l"(B.u), "l"(C.u));
    return D.f;
}
__device__ __forceinline__ float2 fadd2(float2 a, float2 b) {
    f2u A, B, D; A.f = a; B.f = b;
    asm("add.rn.f32x2 %0, %1, %2;" : "=l"(D.u) : "l"(A.u), "l"(B.u));
    return D.f;
}
__device__ __forceinline__ float sqrt_ap(float x) {
    float r; asm("sqrt.approx.f32 %0, %1;" : "=f"(r) : "f"(x)); return r;
}
__device__ __forceinline__ float ex2_ap(float x) {
    float r; asm("ex2.approx.f32 %0, %1;" : "=f"(r) : "f"(x)); return r;
}

// Clipped, LG2E-scaled palette color for query q.
__device__ __forceinline__ float4 query_quad(const float* __restrict__ pallet, int q) {
    float x = fminf(fmaxf(pallet[3 * q]     * 0.5f, 0.f), 1.f);
    float y = fminf(fmaxf(pallet[3 * q + 1] * 0.5f, 0.f), 1.f);
    float z = fminf(fmaxf(pallet[3 * q + 2] * 0.5f, 0.f), 1.f);
    float ax = x * LG2E, ay = y * LG2E, az = z * LG2E;
    return make_float4(ax, ay, az, ax * ax + ay * ay + az * az);
}

// ---------------------------------------------------------------------------
// Fused kernel. Phase A (all 592 blocks): round-9 softmin sweep — pure MUFU
// path, fma+xu pipes co-saturated at the SIMT floor; write chunk partials.
// Phase B (last block per query-column, via threadfence+counter): sum the
// column's 37 chunk partials (303KB, L2-hot), compute closest + MSE terms,
// warp-reduce, atomicAdd into out. No separate reduce launch.
// ---------------------------------------------------------------------------
__global__ void __launch_bounds__(BLK, 4) softmin_kernel(const float* __restrict__ pallet,
                                                         const float* __restrict__ comp,
                                                         float* __restrict__ out) {
    // shared: lane-duplicated key quads: per i, {B2,B2,nx,nx} {ny,ny,nz,nz}
    __shared__ float4 sb[MC * 2];
    __shared__ bool isLast;

    const int m0 = blockIdx.y * MC;
    const int mc = min(MC, N_PTS - m0);
    if (threadIdx.x < mc) {
        const int m = m0 + threadIdx.x;
        float bx = comp[3 * m] * LG2E, by = comp[3 * m + 1] * LG2E, bz = comp[3 * m + 2] * LG2E;
        float b2 = bx * bx + by * by + bz * bz;
        float nx = -2.f * bx, ny = -2.f * by, nz = -2.f * bz;
        sb[2 * threadIdx.x]     = make_float4(b2, b2, nx, nx);
        sb[2 * threadIdx.x + 1] = make_float4(ny, ny, nz, nz);
    }

    const int q0 = blockIdx.x * QCOL + threadIdx.x * Q_PER_THREAD;
    float4 a0 = query_quad(pallet, q0);
    float4 a1 = query_quad(pallet, q0 + 1);
    const float2 Ax = make_float2(a0.x, a1.x);
    const float2 Ay = make_float2(a0.y, a1.y);
    const float2 Az = make_float2(a0.z, a1.z);
    const float2 A2 = make_float2(a0.w, a1.w);
    float2 sw = make_float2(0.f, 0.f), cx = sw, cy = sw, cz = sw;

    __syncthreads();

#pragma unroll 4
    for (int i = 0; i < mc; i++) {
        const float4 u4 = sb[2 * i], v4 = sb[2 * i + 1];
        const float2 B2 = make_float2(u4.x, u4.y);
        const float2 nx = make_float2(u4.z, u4.w);
        const float2 ny = make_float2(v4.x, v4.y);
        const float2 nz = make_float2(v4.z, v4.w);
        // s' = |A|^2 + |B|^2 - 2 A.B  (= log2e^2 * |a-b|^2)
        float2 sv = ffma2(nx, Ax, ffma2(ny, Ay, ffma2(nz, Az, fadd2(B2, A2))));
        // u = log2e * dist; w = 2^(-u) = exp(-dist). |.| and neg fold into MUFU.
        float2 w = make_float2(ex2_ap(-sqrt_ap(fabsf(sv.x))),
                               ex2_ap(-sqrt_ap(fabsf(sv.y))));
        sw = fadd2(sw, w);
        cx = ffma2(w, nx, cx);   // accumulates w*(-2*LG2E*bx) etc.
        cy = ffma2(w, ny, cy);
        cz = ffma2(w, nz, cz);
    }

    float4* dst = g_scratch + blockIdx.y * N_PTS + q0;
    dst[0] = make_float4(sw.x, cx.x, cy.x, cz.x);
    dst[1] = make_float4(sw.y, cx.y, cy.y, cz.y);

    // ---- completion handshake (canonical threadfence-reduction pattern) ----
    __threadfence();
    if (threadIdx.x == 0) {
        unsigned int old = atomicAdd(&g_cnt[blockIdx.x], 1u);
        isLast = (old == NCH - 1);
    }
    __syncthreads();
    if (!isLast) return;
    if (threadIdx.x == 0) g_cnt[blockIdx.x] = 0;   // reset for next graph replay

    // ---- Phase B: reduce this column's 512 queries over 37 chunks ----------
    const int qbase = blockIdx.x * QCOL;
    float local = 0.f;
#pragma unroll
    for (int k = 0; k < Q_PER_THREAD; k++) {
        const int q = qbase + k * BLK + threadIdx.x;   // lane-coalesced float4s
        float rsw = 0.f, rcx = 0.f, rcy = 0.f, rcz = 0.f;
#pragma unroll 8
        for (int ch = 0; ch < NCH; ch++) {
            float4 v = g_scratch[ch * N_PTS + q];
            rsw += v.x; rcx += v.y; rcy += v.z; rcz += v.w;
        }
        // closest_c = acc_c / (-2 * LG2E * sum_w)   (acc holds w * -2*LG2E*b)
        const float inv = -1.f / (2.f * LG2E * rsw);
        float clx = rcx * inv, cly = rcy * inv, clz = rcz * inv;

        float4 a = query_quad(pallet, q);              // LG2E-scaled
        float ex = a.x * ILG2E - clx;
        float ey = a.y * ILG2E - cly;
        float ez = a.z * ILG2E - clz;
        local += ex * ex + ey * ey + ez * ez;
    }

    for (int off = 16; off > 0; off >>= 1)
        local += __shfl_down_sync(0xFFFFFFFFu, local, off);
    if ((threadIdx.x & 31) == 0)
        atomicAdd(out, local * (1.f / (float)(N_PTS * 3)));
}

// ---------------------------------------------------------------------------
extern "C" void kernel_launch(void* const* d_in, const int* in_sizes, int n_in,
                              void* d_out, int out_size) {
    const float* pallet = (const float*)d_in[0];
    const float* comp   = (const float*)d_in[1];
    float* out = (float*)d_out;

    cudaMemsetAsync(out, 0, sizeof(float));
    softmin_kernel<<<dim3(GX, NCH), BLK>>>(pallet, comp, out);
}

// round 13
// speedup vs baseline: 1.0745x; 1.0745x over previous
#include <cuda_runtime.h>
#include <cstdint>

// Problem sizes (fixed by reference)
#define S_DIM  1024
#define P_DIM  8
#define N_PTS  8192            // S*P flattened colors

// NOTE: the reference sorts palette rows per column before the softmin, but
// the final loss is a MEAN over all queries -> permutation-invariant. The
// sort is a no-op on the output scalar and is omitted entirely.

#define Q_PER_THREAD 2         // 1 packed pair per thread
#define BLK          256       // 8 warps/block
#define NCH          37        // key chunks; grid 16 x 37 = 592 = 4 blocks/SM
                               // -> 32 warps/SM = 8 warps/SMSP
#define MC           222       // ceil(8192/37); last chunk = 200 (both even)

// Coordinates pre-scaled by LG2E so u = sqrt(s') = log2(e)*dist and
// exp(-dist) = ex2(-u). Poly path: degree-5 minimax of exp(-u*ln2) on
// u in [0, 2.5] (the r3 fit reparametrized to the LG2E scale).
#define LG2E  1.4426950408889634f
#define ILG2E 0.6931471805599453f
#define P0    1.0000332f
#define P1   -0.6928500f
#define P2    0.2389700f
#define P3   -0.0533300f
#define P4    0.0078085f
#define P5   -0.0005782f

// Static device scratch (no allocations allowed)
__device__ float4 g_scratch[NCH * N_PTS];    // per-chunk partials {sum_w, accx, accy, accz}

// ---- packed f32x2 helpers -------------------------------------------------
union f2u { float2 f; unsigned long long u; };
__device__ __forceinline__ float2 ffma2(float2 a, float2 b, float2 c) {
    f2u A, B, C, D; A.f = a; B.f = b; C.f = c;
    asm("fma.rn.f32x2 %0, %1, %2, %3;" : "=l"(D.u) : "l"(A.u), "l"(B.u), "l"(C.u));
    return D.f;
}
__device__ __forceinline__ float2 fadd2(float2 a, float2 b) {
    f2u A, B, D; A.f = a; B.f = b;
    asm("add.rn.f32x2 %0, %1, %2;" : "=l"(D.u) : "l"(A.u), "l"(B.u));
    return D.f;
}
__device__ __forceinline__ float sqrt_ap(float x) {
    float r; asm("sqrt.approx.f32 %0, %1;" : "=f"(r) : "f"(x)); return r;
}
__device__ __forceinline__ float ex2_ap(float x) {
    float r; asm("ex2.approx.f32 %0, %1;" : "=f"(r) : "f"(x)); return r;
}

// Clipped, LG2E-scaled palette color for query q.
__device__ __forceinline__ float4 query_quad(const float* __restrict__ pallet, int q) {
    float x = fminf(fmaxf(pallet[3 * q]     * 0.5f, 0.f), 1.f);
    float y = fminf(fmaxf(pallet[3 * q + 1] * 0.5f, 0.f), 1.f);
    float z = fminf(fmaxf(pallet[3 * q + 2] * 0.5f, 0.f), 1.f);
    float ax = x * LG2E, ay = y * LG2E, az = z * LG2E;
    return make_float4(ax, ay, az, ax * ax + ay * ay + az * az);
}

// ---------------------------------------------------------------------------
// Phase 1: 8192x8192 softmin sweep. Keys alternate between the ex2 path
// (MUFU-heavy) and a degree-5 Horner poly path (FP32-heavy; sm_100a spreads
// FP32 across both fma and alu pipes) to balance MUFU against issue.
// grid (16, 37), BLK=256, 2 queries per thread, key chunk prepped inline.
// ---------------------------------------------------------------------------
__global__ void __launch_bounds__(BLK, 4) softmin_kernel(const float* __restrict__ pallet,
                                                         const float* __restrict__ comp) {
    // shared: lane-duplicated key quads: per i, {B2,B2,nx,nx} {ny,ny,nz,nz}
    __shared__ float4 sb[MC * 2];

    const int m0 = blockIdx.y * MC;
    const int mc = min(MC, N_PTS - m0);
    if (threadIdx.x < mc) {
        const int m = m0 + threadIdx.x;
        float bx = comp[3 * m] * LG2E, by = comp[3 * m + 1] * LG2E, bz = comp[3 * m + 2] * LG2E;
        float b2 = bx * bx + by * by + bz * bz;
        float nx = -2.f * bx, ny = -2.f * by, nz = -2.f * bz;
        sb[2 * threadIdx.x]     = make_float4(b2, b2, nx, nx);
        sb[2 * threadIdx.x + 1] = make_float4(ny, ny, nz, nz);
    }

    const int q0 = blockIdx.x * (BLK * Q_PER_THREAD) + threadIdx.x * Q_PER_THREAD;
    float4 a0 = query_quad(pallet, q0);
    float4 a1 = query_quad(pallet, q0 + 1);
    const float2 Ax = make_float2(a0.x, a1.x);
    const float2 Ay = make_float2(a0.y, a1.y);
    const float2 Az = make_float2(a0.z, a1.z);
    const float2 A2 = make_float2(a0.w, a1.w);
    float2 sw = make_float2(0.f, 0.f), cx = sw, cy = sw, cz = sw;

    const float2 k0 = make_float2(P0, P0), k1 = make_float2(P1, P1),
                 k2 = make_float2(P2, P2), k3 = make_float2(P3, P3),
                 k4 = make_float2(P4, P4), k5 = make_float2(P5, P5);

    __syncthreads();

#pragma unroll 2
    for (int i = 0; i < mc; i += 2) {
        {   // --- key i: poly path (FP32-heavy) ---
            const float4 u4 = sb[2 * i], v4 = sb[2 * i + 1];
            const float2 B2 = make_float2(u4.x, u4.y);
            const float2 nx = make_float2(u4.z, u4.w);
            const float2 ny = make_float2(v4.x, v4.y);
            const float2 nz = make_float2(v4.z, v4.w);
            float2 sv = ffma2(nx, Ax, ffma2(ny, Ay, ffma2(nz, Az, fadd2(B2, A2))));
            float2 u = make_float2(sqrt_ap(fabsf(sv.x)), sqrt_ap(fabsf(sv.y)));
            float2 w = ffma2(k5, u, k4);              // Horner in u = LG2E*dist
            w = ffma2(w, u, k3);
            w = ffma2(w, u, k2);
            w = ffma2(w, u, k1);
            w = ffma2(w, u, k0);                      // ~= exp(-dist)
            sw = fadd2(sw, w);
            cx = ffma2(w, nx, cx);
            cy = ffma2(w, ny, cy);
            cz = ffma2(w, nz, cz);
        }
        {   // --- key i+1: ex2 path (MUFU-heavy) ---
            const float4 u4 = sb[2 * i + 2], v4 = sb[2 * i + 3];
            const float2 B2 = make_float2(u4.x, u4.y);
            const float2 nx = make_float2(u4.z, u4.w);
            const float2 ny = make_float2(v4.x, v4.y);
            const float2 nz = make_float2(v4.z, v4.w);
            float2 sv = ffma2(nx, Ax, ffma2(ny, Ay, ffma2(nz, Az, fadd2(B2, A2))));
            float2 w = make_float2(ex2_ap(-sqrt_ap(fabsf(sv.x))),
                                   ex2_ap(-sqrt_ap(fabsf(sv.y))));
            sw = fadd2(sw, w);
            cx = ffma2(w, nx, cx);
            cy = ffma2(w, ny, cy);
            cz = ffma2(w, nz, cz);
        }
    }

    float4* dst = g_scratch + blockIdx.y * N_PTS + q0;
    dst[0] = make_float4(sw.x, cx.x, cy.x, cz.x);
    dst[1] = make_float4(sw.y, cx.y, cy.y, cz.y);
}

// ---------------------------------------------------------------------------
// Phase 2: combine chunk partials (coalesced), MSE reduce. Round-9 config
// (measured 6.1us): 256 blocks x 512 threads, lanes = consecutive q,
// warps stride the 37 chunks.
// ---------------------------------------------------------------------------
#define RBLK 512
#define RWARPS (RBLK / 32)
__global__ void __launch_bounds__(RBLK) reduce_kernel(const float* __restrict__ pallet,
                                                      float* __restrict__ out) {
    const int lane = threadIdx.x & 31;
    const int wid  = threadIdx.x >> 5;            // 0..15
    const int q    = blockIdx.x * 32 + lane;

    float sw = 0.f, cx = 0.f, cy = 0.f, cz = 0.f;
#pragma unroll
    for (int ch = wid; ch < NCH; ch += RWARPS) {
        float4 v = g_scratch[ch * N_PTS + q];
        sw += v.x; cx += v.y; cy += v.z; cz += v.w;
    }

    __shared__ float4 part[RWARPS][32];
    part[wid][lane] = make_float4(sw, cx, cy, cz);
    __syncthreads();

    if (wid == 0) {
#pragma unroll
        for (int w = 1; w < RWARPS; w++) {
            float4 v = part[w][lane];
            sw += v.x; cx += v.y; cy += v.z; cz += v.w;
        }
        // closest_c = acc_c / (-2 * LG2E * sum_w)   (acc holds w * -2*LG2E*b)
        const float inv = -1.f / (2.f * LG2E * sw);
        float clx = cx * inv, cly = cy * inv, clz = cz * inv;

        float4 a = query_quad(pallet, q);          // LG2E-scaled
        float ex = a.x * ILG2E - clx;
        float ey = a.y * ILG2E - cly;
        float ez = a.z * ILG2E - clz;
        float local = ex * ex + ey * ey + ez * ez;

        for (int off = 16; off > 0; off >>= 1)
            local += __shfl_down_sync(0xFFFFFFFFu, local, off);
        if (lane == 0)
            atomicAdd(out, local * (1.f / (float)(N_PTS * 3)));
    }
}

// ---------------------------------------------------------------------------
extern "C" void kernel_launch(void* const* d_in, const int* in_sizes, int n_in,
                              void* d_out, int out_size) {
    const float* pallet = (const float*)d_in[0];
    const float* comp   = (const float*)d_in[1];
    float* out = (float*)d_out;

    cudaMemsetAsync(out, 0, sizeof(float));
    softmin_kernel<<<dim3(N_PTS / (BLK * Q_PER_THREAD), NCH), BLK>>>(pallet, comp);
    reduce_kernel<<<N_PTS / 32, RBLK>>>(pallet, out);
}